// round 14
// baseline (speedup 1.0000x reference)
#include <cuda_runtime.h>
#include <cuda_fp16.h>
#include <cstdint>

#define N_NODES 40000
#define N_EDGES 640000
#define IN_DIM  128
#define HID     256

#define SCAN_BLOCKS 40
#define SCAN_CHUNK  1000   // 40 * 1000 = 40000 exactly

// ---------------- device scratch (static, no allocations) ----------------
__device__ int   g_is64;
__device__ int   g_count[N_NODES];
__device__ int   g_rowstart[N_NODES + 1];
__device__ int   g_cursor[N_NODES];
__device__ int   g_src[N_EDGES];
__device__ volatile int g_bsum[SCAN_BLOCKS];
__device__ volatile int g_bflag[SCAN_BLOCKS];

#define WO_L1 0
#define WO_R1 (HID * IN_DIM)
#define WO_L2 (2 * HID * IN_DIM)
#define WO_R2 (2 * HID * IN_DIM + HID * HID)
#define WO_L3 (2 * HID * IN_DIM + 2 * HID * HID)
#define WO_R3 (2 * HID * IN_DIM + 3 * HID * HID)
#define W_TOTAL (2 * HID * IN_DIM + 4 * HID * HID)
#define NX (N_NODES * IN_DIM)

__device__ __align__(16) __half g_xh [(size_t)NX];
__device__ __align__(16) __half g_wh [W_TOTAL];
__device__ __align__(16) __half g_agg[(size_t)N_NODES * HID];
__device__ __align__(16) __half g_h  [(size_t)N_NODES * HID];
__device__ __align__(16) __half g_h2 [(size_t)N_NODES * HID];

__device__ __forceinline__ int clampN(int v) {
    return v < 0 ? 0 : (v >= N_NODES ? N_NODES - 1 : v);
}

// ---------------- fused init: zero counts/flags + dtype detect + fp16 convert
__global__ void k_init_convert(const int* __restrict__ ei_w,
                               const float* __restrict__ x,
                               const float* __restrict__ Wl1, const float* __restrict__ Wr1,
                               const float* __restrict__ Wl2, const float* __restrict__ Wr2,
                               const float* __restrict__ Wl3, const float* __restrict__ Wr3) {
    int i = blockIdx.x * blockDim.x + threadIdx.x;
    if (i < N_NODES) g_count[i] = 0;
    if (i < SCAN_BLOCKS) { g_bflag[i] = 0; g_bsum[i] = 0; }
    if (blockIdx.x == 0) {
        __shared__ int acc;
        if (threadIdx.x == 0) acc = 0;
        __syncthreads();
        int v = 0;
        for (int j = threadIdx.x; j < 2048; j += 256) v |= ei_w[2 * j + 1];
        atomicOr(&acc, v);
        __syncthreads();
        if (threadIdx.x == 0) g_is64 = (acc == 0) ? 1 : 0;
    }
    if (i < NX) {
        g_xh[i] = __float2half_rn(x[i]);
        return;
    }
    int j = i - NX;
    if (j >= W_TOTAL) return;
    float v;
    if      (j < WO_R1) v = Wl1[j - WO_L1];
    else if (j < WO_L2) v = Wr1[j - WO_R1];
    else if (j < WO_R2) v = Wl2[j - WO_L2];
    else if (j < WO_L3) v = Wr2[j - WO_R2];
    else if (j < WO_R3) v = Wl3[j - WO_L3];
    else                v = Wr3[j - WO_R3];
    g_wh[j] = __float2half_rn(v);
}

// ---------------- degree histogram (reads edge buffer directly) ----------
__global__ void k_count_dst(const int* __restrict__ ei_w) {
    int e = blockIdx.x * blockDim.x + threadIdx.x;
    if (e >= N_EDGES) return;
    int d = g_is64 ? ei_w[2 * ((size_t)N_EDGES + e)] : ei_w[N_EDGES + e];
    atomicAdd(&g_count[clampN(d)], 1);
}

// ---------------- single-kernel decoupled-lookback scan -------------------
// 40 co-resident blocks; publish-then-wait => deadlock-free.
__global__ void k_scan() {
    __shared__ int sm[1024];
    __shared__ int s_off;
    const int b = blockIdx.x, t = threadIdx.x;
    const int idx = b * SCAN_CHUNK + t;
    int v = (t < SCAN_CHUNK) ? g_count[idx] : 0;
    sm[t] = v;
    __syncthreads();
    for (int off = 1; off < 1024; off <<= 1) {
        int u = (t >= off) ? sm[t - off] : 0;
        __syncthreads();
        sm[t] += u;
        __syncthreads();
    }
    // publish this block's total FIRST
    if (t == 1023) {
        g_bsum[b] = sm[1023];
        __threadfence();
        g_bflag[b] = 1;
    }
    // thread 0 accumulates predecessor totals
    if (t == 0) {
        int off = 0;
        for (int i = 0; i < b; i++) {
            while (g_bflag[i] == 0) { }
            off += g_bsum[i];
        }
        s_off = off;
    }
    __syncthreads();
    const int off = s_off;
    if (t < SCAN_CHUNK) {
        int rs = sm[t] - v + off;           // exclusive prefix + block offset
        g_rowstart[idx] = rs;
        g_cursor[idx]   = rs;
    }
    if (b == SCAN_BLOCKS - 1 && t == 1023)
        g_rowstart[N_NODES] = off + sm[1023];
}

// ---------------- CSR fill (reads edge buffer directly) -------------------
__global__ void k_fill_src(const int* __restrict__ ei_w) {
    int e = blockIdx.x * blockDim.x + threadIdx.x;
    if (e >= N_EDGES) return;
    int s, d;
    if (g_is64) {
        s = ei_w[2 * (size_t)e];
        d = ei_w[2 * ((size_t)N_EDGES + e)];
    } else {
        s = ei_w[e];
        d = ei_w[N_EDGES + e];
    }
    int pos = atomicAdd(&g_cursor[clampN(d)], 1);
    g_src[pos] = clampN(s);
}

// ---------------- mean aggregation over in-edges (fp16 in/out, fp32 acc) ----
// 8-edge unroll -> 8 outstanding 16B loads per thread for latency hiding.
template <int D>
__global__ void k_aggregate_h(const __half* __restrict__ x, __half* __restrict__ out) {
    constexpr int TPN = D / 8;        // threads per node, uint4 = 8 halves
    constexpr int NPB = 256 / TPN;
    int node = blockIdx.x * NPB + threadIdx.x / TPN;
    int lane = threadIdx.x % TPN;
    if (node >= N_NODES) return;

    const int beg = g_rowstart[node];
    const int end = g_rowstart[node + 1];
    const uint4* xv = (const uint4*)x;

    float acc[8] = {};
    int j = beg;
    for (; j + 8 <= end; j += 8) {
        uint4 v[8];
        #pragma unroll
        for (int e = 0; e < 8; e++)
            v[e] = xv[(size_t)g_src[j + e] * TPN + lane];
        #pragma unroll
        for (int e = 0; e < 8; e++) {
            #pragma unroll
            for (int q = 0; q < 4; q++) {
                uint32_t w = (&v[e].x)[q];
                float2 f = __half22float2(*(__half2*)&w);
                acc[2 * q + 0] += f.x;
                acc[2 * q + 1] += f.y;
            }
        }
    }
    for (; j + 4 <= end; j += 4) {
        uint4 v[4];
        #pragma unroll
        for (int e = 0; e < 4; e++)
            v[e] = xv[(size_t)g_src[j + e] * TPN + lane];
        #pragma unroll
        for (int e = 0; e < 4; e++) {
            #pragma unroll
            for (int q = 0; q < 4; q++) {
                uint32_t w = (&v[e].x)[q];
                float2 f = __half22float2(*(__half2*)&w);
                acc[2 * q + 0] += f.x;
                acc[2 * q + 1] += f.y;
            }
        }
    }
    for (; j < end; j++) {
        uint4 v = xv[(size_t)g_src[j] * TPN + lane];
        #pragma unroll
        for (int q = 0; q < 4; q++) {
            uint32_t w = (&v.x)[q];
            float2 f = __half22float2(*(__half2*)&w);
            acc[2 * q + 0] += f.x;
            acc[2 * q + 1] += f.y;
        }
    }
    float inv = (end > beg) ? 1.f / (float)(end - beg) : 0.f;
    uint4 r;
    #pragma unroll
    for (int q = 0; q < 4; q++) {
        __half2 hp = __floats2half2_rn(acc[2 * q] * inv, acc[2 * q + 1] * inv);
        (&r.x)[q] = *(uint32_t*)&hp;
    }
    ((uint4*)out)[(size_t)node * TPN + lane] = r;
}

// ---------------- fp16 tensor-core fused dual-source GEMM (proven) ----------
// C[M,256] = A0@W0^T + A1@W1^T + b (optional ReLU); fp32 accumulate.
// BM=BN=128, BK=32 halves; 4-stage cp.async, issue distance 2, one barrier/tile.
__device__ __forceinline__ void mma_f16(float* c,
                                        uint32_t a0, uint32_t a1, uint32_t a2, uint32_t a3,
                                        uint32_t b0, uint32_t b1) {
    asm volatile(
        "mma.sync.aligned.m16n8k16.row.col.f32.f16.f16.f32 "
        "{%0,%1,%2,%3}, {%4,%5,%6,%7}, {%8,%9}, {%0,%1,%2,%3};"
        : "+f"(c[0]), "+f"(c[1]), "+f"(c[2]), "+f"(c[3])
        : "r"(a0), "r"(a1), "r"(a2), "r"(a3), "r"(b0), "r"(b1));
}

#define GLDS  40                       // halves per smem row (80 B)
#define GTILE (128 * GLDS)             // halves per stage buffer (10 KB)
#define GSMEM (8 * GTILE * 2)          // 4 A stages + 4 B stages = 81920 B

__global__ __launch_bounds__(256, 2)
void k_gemm_h(const __half* __restrict__ A0, const __half* __restrict__ W0,
              const __half* __restrict__ A1, const __half* __restrict__ W1,
              int K, const float* __restrict__ bias,
              void* __restrict__ Cout, int relu_half) {
    extern __shared__ __half smh[];    // [As0..As3 | Bs0..Bs3]

    const int t    = threadIdx.x;
    const int warp = t >> 5, lane = t & 31;
    const int g    = lane >> 2, tg = lane & 3;
    const int wm   = warp & 3;                 // M offset 32*wm
    const int wn   = warp >> 2;                // N offset 64*wn
    const int row0 = blockIdx.x * 128;
    const int col0 = blockIdx.y * 128;

    const int lr = t >> 2;                     // 0..63 load row (2 passes)
    const int kq = t & 3;                      // 0..3, 16B (8-half) chunk

    const int tilesPerSrc = K >> 5;
    const int nTiles = 2 * tilesPerSrc;

    float acc[2][8][4] = {};

    auto issue = [&](int tile) {
        const int s = tile & 3;
        const __half* A = (tile < tilesPerSrc) ? A0 : A1;
        const __half* W = (tile < tilesPerSrc) ? W0 : W1;
        const int kt = ((tile < tilesPerSrc) ? tile : tile - tilesPerSrc) << 5;
        #pragma unroll
        for (int p = 0; p < 2; p++) {
            int row = lr + 64 * p;
            uint32_t da = (uint32_t)__cvta_generic_to_shared(
                &smh[s * GTILE + row * GLDS + kq * 8]);
            const __half* ga = &A[(size_t)(row0 + row) * K + kt + kq * 8];
            int sz = (row0 + row < N_NODES) ? 16 : 0;
            asm volatile("cp.async.cg.shared.global [%0], [%1], 16, %2;"
                         :: "r"(da), "l"(ga), "r"(sz));
            uint32_t db = (uint32_t)__cvta_generic_to_shared(
                &smh[4 * GTILE + s * GTILE + row * GLDS + kq * 8]);
            const __half* gw = &W[(size_t)(col0 + row) * K + kt + kq * 8];
            asm volatile("cp.async.cg.shared.global [%0], [%1], 16;"
                         :: "r"(db), "l"(gw));
        }
        asm volatile("cp.async.commit_group;");
    };

    issue(0);
    issue(1);
    for (int tile = 0; tile < nTiles; ++tile) {
        if (tile + 2 < nTiles) {
            issue(tile + 2);
            asm volatile("cp.async.wait_group 2;");
        } else if (tile + 1 < nTiles) {
            asm volatile("cp.async.wait_group 1;");
        } else {
            asm volatile("cp.async.wait_group 0;");
        }
        __syncthreads();                        // single barrier per tile

        const __half* Asb = &smh[(tile & 3) * GTILE];
        const __half* Bsb = &smh[4 * GTILE + (tile & 3) * GTILE];

        #pragma unroll
        for (int kk = 0; kk < 32; kk += 16) {
            uint32_t bf[8][2];
            #pragma unroll
            for (int nt = 0; nt < 8; nt++) {
                int n = wn * 64 + nt * 8 + g;
                bf[nt][0] = *(const uint32_t*)&Bsb[n * GLDS + kk + 2 * tg];
                bf[nt][1] = *(const uint32_t*)&Bsb[n * GLDS + kk + 2 * tg + 8];
            }
            #pragma unroll
            for (int mt = 0; mt < 2; mt++) {
                int r = wm * 32 + mt * 16 + g;
                uint32_t a0 = *(const uint32_t*)&Asb[(r    ) * GLDS + kk + 2 * tg];
                uint32_t a1 = *(const uint32_t*)&Asb[(r + 8) * GLDS + kk + 2 * tg];
                uint32_t a2 = *(const uint32_t*)&Asb[(r    ) * GLDS + kk + 2 * tg + 8];
                uint32_t a3 = *(const uint32_t*)&Asb[(r + 8) * GLDS + kk + 2 * tg + 8];
                #pragma unroll
                for (int nt = 0; nt < 8; nt++)
                    mma_f16(acc[mt][nt], a0, a1, a2, a3, bf[nt][0], bf[nt][1]);
            }
        }
    }

    // epilogue: bias; relu+fp16 store (layers 1-2) or fp32 store (layer 3)
    #pragma unroll
    for (int mt = 0; mt < 2; mt++) {
        int r = row0 + wm * 32 + mt * 16 + g;
        #pragma unroll
        for (int nt = 0; nt < 8; nt++) {
            int col = col0 + wn * 64 + nt * 8 + tg * 2;
            float2 bv = *(const float2*)&bias[col];
            float v0 = acc[mt][nt][0] + bv.x;
            float v1 = acc[mt][nt][1] + bv.y;
            float v2 = acc[mt][nt][2] + bv.x;
            float v3 = acc[mt][nt][3] + bv.y;
            if (relu_half) {
                __half* C = (__half*)Cout;
                __half2 h0 = __floats2half2_rn(fmaxf(v0, 0.f), fmaxf(v1, 0.f));
                __half2 h1 = __floats2half2_rn(fmaxf(v2, 0.f), fmaxf(v3, 0.f));
                if (r < N_NODES)     *(__half2*)&C[(size_t)r * HID + col]       = h0;
                if (r + 8 < N_NODES) *(__half2*)&C[(size_t)(r + 8) * HID + col] = h1;
            } else {
                float* C = (float*)Cout;
                if (r < N_NODES)     *(float2*)&C[(size_t)r * HID + col]       = make_float2(v0, v1);
                if (r + 8 < N_NODES) *(float2*)&C[(size_t)(r + 8) * HID + col] = make_float2(v2, v3);
            }
        }
    }
}

// ---------------- launch ----------------
extern "C" void kernel_launch(void* const* d_in, const int* in_sizes, int n_in,
                              void* d_out, int out_size) {
    const float* x   = (const float*)d_in[0];
    const int*   eiw = (const int*)d_in[1];
    const float* Wl1 = (const float*)d_in[2];
    const float* Wr1 = (const float*)d_in[3];
    const float* b1  = (const float*)d_in[4];
    const float* Wl2 = (const float*)d_in[5];
    const float* Wr2 = (const float*)d_in[6];
    const float* b2  = (const float*)d_in[7];
    const float* Wl3 = (const float*)d_in[8];
    const float* Wr3 = (const float*)d_in[9];
    const float* b3  = (const float*)d_in[10];
    float*       out = (float*)d_out;

    __half *agg, *h, *h2, *xh, *wh;
    cudaGetSymbolAddress((void**)&agg, g_agg);
    cudaGetSymbolAddress((void**)&h,   g_h);
    cudaGetSymbolAddress((void**)&h2,  g_h2);
    cudaGetSymbolAddress((void**)&xh,  g_xh);
    cudaGetSymbolAddress((void**)&wh,  g_wh);

    cudaFuncSetAttribute(k_gemm_h,
                         cudaFuncAttributeMaxDynamicSharedMemorySize, GSMEM);

    // fused init (zero + detect + convert), then lean CSR build (3 kernels)
    k_init_convert<<<(NX + W_TOTAL + 255) / 256, 256>>>(eiw, x, Wl1, Wr1,
                                                        Wl2, Wr2, Wl3, Wr3);
    k_count_dst<<<(N_EDGES + 255) / 256, 256>>>(eiw);
    k_scan<<<SCAN_BLOCKS, 1024>>>();
    k_fill_src<<<(N_EDGES + 255) / 256, 256>>>(eiw);

    dim3 ggrid((N_NODES + 127) / 128, HID / 128);   // 313 x 2

    // Layer 1: 128 -> 256, relu, fp16 out
    k_aggregate_h<IN_DIM><<<(N_NODES + 15) / 16, 256>>>(xh, agg);
    k_gemm_h<<<ggrid, 256, GSMEM>>>(agg, wh + WO_L1, xh, wh + WO_R1,
                                    IN_DIM, b1, h, 1);

    // Layer 2: 256 -> 256, relu, fp16 out
    k_aggregate_h<HID><<<(N_NODES + 7) / 8, 256>>>(h, agg);
    k_gemm_h<<<ggrid, 256, GSMEM>>>(agg, wh + WO_L2, h, wh + WO_R2,
                                    HID, b2, h2, 1);

    // Layer 3: 256 -> 256, fp32 out to d_out
    k_aggregate_h<HID><<<(N_NODES + 7) / 8, 256>>>(h2, agg);
    k_gemm_h<<<ggrid, 256, GSMEM>>>(agg, wh + WO_L3, h2, wh + WO_R3,
                                    HID, b3, out, 0);
}

// round 15
// speedup vs baseline: 1.0496x; 1.0496x over previous
#include <cuda_runtime.h>
#include <cuda_fp16.h>
#include <cstdint>

#define N_NODES 40000
#define N_EDGES 640000
#define IN_DIM  128
#define HID     256

#define SCAN_BLOCKS 40
#define SCAN_CHUNK  1000   // 40 * 1000 = 40000 exactly

// ---------------- device scratch (static, no allocations) ----------------
__device__ int   g_is64;
__device__ int   g_srcs[N_EDGES];
__device__ int   g_dsts[N_EDGES];
__device__ int   g_count[N_NODES];
__device__ int   g_rowstart[N_NODES + 1];
__device__ int   g_cursor[N_NODES];
__device__ int   g_src[N_EDGES];
__device__ int   g_blocksum[SCAN_BLOCKS];

#define WO_L1 0
#define WO_R1 (HID * IN_DIM)
#define WO_L2 (2 * HID * IN_DIM)
#define WO_R2 (2 * HID * IN_DIM + HID * HID)
#define WO_L3 (2 * HID * IN_DIM + 2 * HID * HID)
#define WO_R3 (2 * HID * IN_DIM + 3 * HID * HID)
#define W_TOTAL (2 * HID * IN_DIM + 4 * HID * HID)
#define NX (N_NODES * IN_DIM)

__device__ __align__(16) __half g_xh [(size_t)NX];
__device__ __align__(16) __half g_wh [W_TOTAL];
__device__ __align__(16) __half g_agg[(size_t)N_NODES * HID];
__device__ __align__(16) __half g_h  [(size_t)N_NODES * HID];
__device__ __align__(16) __half g_h2 [(size_t)N_NODES * HID];

// ---------------- fused init: zero counts + dtype detect + fp16 convert -----
__global__ void k_init_convert(const int* __restrict__ ei_w,
                               const float* __restrict__ x,
                               const float* __restrict__ Wl1, const float* __restrict__ Wr1,
                               const float* __restrict__ Wl2, const float* __restrict__ Wr2,
                               const float* __restrict__ Wl3, const float* __restrict__ Wr3) {
    int i = blockIdx.x * blockDim.x + threadIdx.x;
    if (i < N_NODES) g_count[i] = 0;
    if (blockIdx.x == 0) {
        __shared__ int acc;
        if (threadIdx.x == 0) acc = 0;
        __syncthreads();
        int v = 0;
        for (int j = threadIdx.x; j < 2048; j += 256) v |= ei_w[2 * j + 1];
        atomicOr(&acc, v);
        __syncthreads();
        if (threadIdx.x == 0) g_is64 = (acc == 0) ? 1 : 0;
    }
    if (i < NX) {
        g_xh[i] = __float2half_rn(x[i]);
        return;
    }
    int j = i - NX;
    if (j >= W_TOTAL) return;
    float v;
    if      (j < WO_R1) v = Wl1[j - WO_L1];
    else if (j < WO_L2) v = Wr1[j - WO_R1];
    else if (j < WO_R2) v = Wl2[j - WO_L2];
    else if (j < WO_L3) v = Wr2[j - WO_R2];
    else if (j < WO_R3) v = Wl3[j - WO_L3];
    else                v = Wr3[j - WO_R3];
    g_wh[j] = __float2half_rn(v);
}

__device__ __forceinline__ int clampN(int v) {
    return v < 0 ? 0 : (v >= N_NODES ? N_NODES - 1 : v);
}

// normalize edge list + histogram; int64 path uses coalesced 64-bit loads
__global__ void k_extract_count(const int* __restrict__ ei_w) {
    int e = blockIdx.x * blockDim.x + threadIdx.x;
    if (e >= N_EDGES) return;
    int s, d;
    if (g_is64) {
        const int2* ei64 = (const int2*)ei_w;     // one aligned 8B load each
        s = ei64[(size_t)e].x;
        d = ei64[(size_t)N_EDGES + e].x;
    } else {
        s = ei_w[e];
        d = ei_w[N_EDGES + e];
    }
    s = clampN(s); d = clampN(d);
    g_srcs[e] = s;
    g_dsts[e] = d;
    atomicAdd(&g_count[d], 1);
}

// ---------------- decoupled scan ----------------
__global__ void k_scan_phase1() {
    __shared__ int sm[1024];
    const int b = blockIdx.x, t = threadIdx.x;
    const int idx = b * SCAN_CHUNK + t;
    int v = (t < SCAN_CHUNK) ? g_count[idx] : 0;
    sm[t] = v;
    __syncthreads();
    for (int off = 1; off < 1024; off <<= 1) {
        int u = (t >= off) ? sm[t - off] : 0;
        __syncthreads();
        sm[t] += u;
        __syncthreads();
    }
    if (t < SCAN_CHUNK) g_rowstart[idx] = sm[t] - v;
    if (t == 1023) g_blocksum[b] = sm[1023];
}

__global__ void k_scan_phase23() {
    __shared__ int off_total[2];
    const int b = blockIdx.x, t = threadIdx.x;
    if (t == 0) {
        int run = 0;
        for (int i = 0; i < SCAN_BLOCKS; i++) {
            if (i == b) off_total[0] = run;
            run += g_blocksum[i];
        }
        off_total[1] = run;
    }
    __syncthreads();
    if (t < SCAN_CHUNK) {
        int idx = b * SCAN_CHUNK + t;
        int rs = g_rowstart[idx] + off_total[0];
        g_rowstart[idx] = rs;
        g_cursor[idx]   = rs;
    }
    if (b == 0 && t == 0) g_rowstart[N_NODES] = off_total[1];
}

__global__ void k_fill_src() {
    int e = blockIdx.x * blockDim.x + threadIdx.x;
    if (e < N_EDGES) {
        int pos = atomicAdd(&g_cursor[g_dsts[e]], 1);
        g_src[pos] = g_srcs[e];
    }
}

// ---------------- mean aggregation over in-edges (fp16 in/out, fp32 acc) ----
// 8-edge unroll -> 8 outstanding 16B loads per thread for latency hiding.
template <int D>
__global__ void k_aggregate_h(const __half* __restrict__ x, __half* __restrict__ out) {
    constexpr int TPN = D / 8;        // threads per node, uint4 = 8 halves
    constexpr int NPB = 256 / TPN;
    int node = blockIdx.x * NPB + threadIdx.x / TPN;
    int lane = threadIdx.x % TPN;
    if (node >= N_NODES) return;

    const int beg = g_rowstart[node];
    const int end = g_rowstart[node + 1];
    const uint4* xv = (const uint4*)x;

    float acc[8] = {};
    int j = beg;
    for (; j + 8 <= end; j += 8) {
        uint4 v[8];
        #pragma unroll
        for (int e = 0; e < 8; e++)
            v[e] = xv[(size_t)g_src[j + e] * TPN + lane];
        #pragma unroll
        for (int e = 0; e < 8; e++) {
            #pragma unroll
            for (int q = 0; q < 4; q++) {
                uint32_t w = (&v[e].x)[q];
                float2 f = __half22float2(*(__half2*)&w);
                acc[2 * q + 0] += f.x;
                acc[2 * q + 1] += f.y;
            }
        }
    }
    for (; j + 4 <= end; j += 4) {
        uint4 v[4];
        #pragma unroll
        for (int e = 0; e < 4; e++)
            v[e] = xv[(size_t)g_src[j + e] * TPN + lane];
        #pragma unroll
        for (int e = 0; e < 4; e++) {
            #pragma unroll
            for (int q = 0; q < 4; q++) {
                uint32_t w = (&v[e].x)[q];
                float2 f = __half22float2(*(__half2*)&w);
                acc[2 * q + 0] += f.x;
                acc[2 * q + 1] += f.y;
            }
        }
    }
    for (; j < end; j++) {
        uint4 v = xv[(size_t)g_src[j] * TPN + lane];
        #pragma unroll
        for (int q = 0; q < 4; q++) {
            uint32_t w = (&v.x)[q];
            float2 f = __half22float2(*(__half2*)&w);
            acc[2 * q + 0] += f.x;
            acc[2 * q + 1] += f.y;
        }
    }
    float inv = (end > beg) ? 1.f / (float)(end - beg) : 0.f;
    uint4 r;
    #pragma unroll
    for (int q = 0; q < 4; q++) {
        __half2 hp = __floats2half2_rn(acc[2 * q] * inv, acc[2 * q + 1] * inv);
        (&r.x)[q] = *(uint32_t*)&hp;
    }
    ((uint4*)out)[(size_t)node * TPN + lane] = r;
}

// ---------------- fp16 tensor-core fused dual-source GEMM (proven) ----------
// C[M,256] = A0@W0^T + A1@W1^T + b (optional ReLU); fp32 accumulate.
// BM=BN=128, BK=32 halves; 4-stage cp.async, issue distance 2, one barrier/tile.
__device__ __forceinline__ void mma_f16(float* c,
                                        uint32_t a0, uint32_t a1, uint32_t a2, uint32_t a3,
                                        uint32_t b0, uint32_t b1) {
    asm volatile(
        "mma.sync.aligned.m16n8k16.row.col.f32.f16.f16.f32 "
        "{%0,%1,%2,%3}, {%4,%5,%6,%7}, {%8,%9}, {%0,%1,%2,%3};"
        : "+f"(c[0]), "+f"(c[1]), "+f"(c[2]), "+f"(c[3])
        : "r"(a0), "r"(a1), "r"(a2), "r"(a3), "r"(b0), "r"(b1));
}

#define GLDS  40                       // halves per smem row (80 B)
#define GTILE (128 * GLDS)             // halves per stage buffer (10 KB)
#define GSMEM (8 * GTILE * 2)          // 4 A stages + 4 B stages = 81920 B

__global__ __launch_bounds__(256, 2)
void k_gemm_h(const __half* __restrict__ A0, const __half* __restrict__ W0,
              const __half* __restrict__ A1, const __half* __restrict__ W1,
              int K, const float* __restrict__ bias,
              void* __restrict__ Cout, int relu_half) {
    extern __shared__ __half smh[];    // [As0..As3 | Bs0..Bs3]

    const int t    = threadIdx.x;
    const int warp = t >> 5, lane = t & 31;
    const int g    = lane >> 2, tg = lane & 3;
    const int wm   = warp & 3;                 // M offset 32*wm
    const int wn   = warp >> 2;                // N offset 64*wn
    const int row0 = blockIdx.x * 128;
    const int col0 = blockIdx.y * 128;

    const int lr = t >> 2;                     // 0..63 load row (2 passes)
    const int kq = t & 3;                      // 0..3, 16B (8-half) chunk

    const int tilesPerSrc = K >> 5;
    const int nTiles = 2 * tilesPerSrc;

    float acc[2][8][4] = {};

    auto issue = [&](int tile) {
        const int s = tile & 3;
        const __half* A = (tile < tilesPerSrc) ? A0 : A1;
        const __half* W = (tile < tilesPerSrc) ? W0 : W1;
        const int kt = ((tile < tilesPerSrc) ? tile : tile - tilesPerSrc) << 5;
        #pragma unroll
        for (int p = 0; p < 2; p++) {
            int row = lr + 64 * p;
            uint32_t da = (uint32_t)__cvta_generic_to_shared(
                &smh[s * GTILE + row * GLDS + kq * 8]);
            const __half* ga = &A[(size_t)(row0 + row) * K + kt + kq * 8];
            int sz = (row0 + row < N_NODES) ? 16 : 0;
            asm volatile("cp.async.cg.shared.global [%0], [%1], 16, %2;"
                         :: "r"(da), "l"(ga), "r"(sz));
            uint32_t db = (uint32_t)__cvta_generic_to_shared(
                &smh[4 * GTILE + s * GTILE + row * GLDS + kq * 8]);
            const __half* gw = &W[(size_t)(col0 + row) * K + kt + kq * 8];
            asm volatile("cp.async.cg.shared.global [%0], [%1], 16;"
                         :: "r"(db), "l"(gw));
        }
        asm volatile("cp.async.commit_group;");
    };

    issue(0);
    issue(1);
    for (int tile = 0; tile < nTiles; ++tile) {
        if (tile + 2 < nTiles) {
            issue(tile + 2);
            asm volatile("cp.async.wait_group 2;");
        } else if (tile + 1 < nTiles) {
            asm volatile("cp.async.wait_group 1;");
        } else {
            asm volatile("cp.async.wait_group 0;");
        }
        __syncthreads();                        // single barrier per tile

        const __half* Asb = &smh[(tile & 3) * GTILE];
        const __half* Bsb = &smh[4 * GTILE + (tile & 3) * GTILE];

        #pragma unroll
        for (int kk = 0; kk < 32; kk += 16) {
            uint32_t bf[8][2];
            #pragma unroll
            for (int nt = 0; nt < 8; nt++) {
                int n = wn * 64 + nt * 8 + g;
                bf[nt][0] = *(const uint32_t*)&Bsb[n * GLDS + kk + 2 * tg];
                bf[nt][1] = *(const uint32_t*)&Bsb[n * GLDS + kk + 2 * tg + 8];
            }
            #pragma unroll
            for (int mt = 0; mt < 2; mt++) {
                int r = wm * 32 + mt * 16 + g;
                uint32_t a0 = *(const uint32_t*)&Asb[(r    ) * GLDS + kk + 2 * tg];
                uint32_t a1 = *(const uint32_t*)&Asb[(r + 8) * GLDS + kk + 2 * tg];
                uint32_t a2 = *(const uint32_t*)&Asb[(r    ) * GLDS + kk + 2 * tg + 8];
                uint32_t a3 = *(const uint32_t*)&Asb[(r + 8) * GLDS + kk + 2 * tg + 8];
                #pragma unroll
                for (int nt = 0; nt < 8; nt++)
                    mma_f16(acc[mt][nt], a0, a1, a2, a3, bf[nt][0], bf[nt][1]);
            }
        }
    }

    // epilogue: bias; relu+fp16 store (layers 1-2) or fp32 store (layer 3)
    #pragma unroll
    for (int mt = 0; mt < 2; mt++) {
        int r = row0 + wm * 32 + mt * 16 + g;
        #pragma unroll
        for (int nt = 0; nt < 8; nt++) {
            int col = col0 + wn * 64 + nt * 8 + tg * 2;
            float2 bv = *(const float2*)&bias[col];
            float v0 = acc[mt][nt][0] + bv.x;
            float v1 = acc[mt][nt][1] + bv.y;
            float v2 = acc[mt][nt][2] + bv.x;
            float v3 = acc[mt][nt][3] + bv.y;
            if (relu_half) {
                __half* C = (__half*)Cout;
                __half2 h0 = __floats2half2_rn(fmaxf(v0, 0.f), fmaxf(v1, 0.f));
                __half2 h1 = __floats2half2_rn(fmaxf(v2, 0.f), fmaxf(v3, 0.f));
                if (r < N_NODES)     *(__half2*)&C[(size_t)r * HID + col]       = h0;
                if (r + 8 < N_NODES) *(__half2*)&C[(size_t)(r + 8) * HID + col] = h1;
            } else {
                float* C = (float*)Cout;
                if (r < N_NODES)     *(float2*)&C[(size_t)r * HID + col]       = make_float2(v0, v1);
                if (r + 8 < N_NODES) *(float2*)&C[(size_t)(r + 8) * HID + col] = make_float2(v2, v3);
            }
        }
    }
}

// ---------------- launch ----------------
extern "C" void kernel_launch(void* const* d_in, const int* in_sizes, int n_in,
                              void* d_out, int out_size) {
    const float* x   = (const float*)d_in[0];
    const int*   eiw = (const int*)d_in[1];
    const float* Wl1 = (const float*)d_in[2];
    const float* Wr1 = (const float*)d_in[3];
    const float* b1  = (const float*)d_in[4];
    const float* Wl2 = (const float*)d_in[5];
    const float* Wr2 = (const float*)d_in[6];
    const float* b2  = (const float*)d_in[7];
    const float* Wl3 = (const float*)d_in[8];
    const float* Wr3 = (const float*)d_in[9];
    const float* b3  = (const float*)d_in[10];
    float*       out = (float*)d_out;

    __half *agg, *h, *h2, *xh, *wh;
    cudaGetSymbolAddress((void**)&agg, g_agg);
    cudaGetSymbolAddress((void**)&h,   g_h);
    cudaGetSymbolAddress((void**)&h2,  g_h2);
    cudaGetSymbolAddress((void**)&xh,  g_xh);
    cudaGetSymbolAddress((void**)&wh,  g_wh);

    cudaFuncSetAttribute(k_gemm_h,
                         cudaFuncAttributeMaxDynamicSharedMemorySize, GSMEM);

    // fused init (zero counts + detect + fp16 convert), then CSR build
    k_init_convert<<<(NX + W_TOTAL + 255) / 256, 256>>>(eiw, x, Wl1, Wr1,
                                                        Wl2, Wr2, Wl3, Wr3);
    k_extract_count<<<(N_EDGES + 255) / 256, 256>>>(eiw);
    k_scan_phase1<<<SCAN_BLOCKS, 1024>>>();
    k_scan_phase23<<<SCAN_BLOCKS, 1024>>>();
    k_fill_src<<<(N_EDGES + 255) / 256, 256>>>();

    dim3 ggrid((N_NODES + 127) / 128, HID / 128);   // 313 x 2

    // Layer 1: 128 -> 256, relu, fp16 out
    k_aggregate_h<IN_DIM><<<(N_NODES + 15) / 16, 256>>>(xh, agg);
    k_gemm_h<<<ggrid, 256, GSMEM>>>(agg, wh + WO_L1, xh, wh + WO_R1,
                                    IN_DIM, b1, h, 1);

    // Layer 2: 256 -> 256, relu, fp16 out
    k_aggregate_h<HID><<<(N_NODES + 7) / 8, 256>>>(h, agg);
    k_gemm_h<<<ggrid, 256, GSMEM>>>(agg, wh + WO_L2, h, wh + WO_R2,
                                    HID, b2, h2, 1);

    // Layer 3: 256 -> 256, fp32 out to d_out
    k_aggregate_h<HID><<<(N_NODES + 7) / 8, 256>>>(h2, agg);
    k_gemm_h<<<ggrid, 256, GSMEM>>>(agg, wh + WO_L3, h2, wh + WO_R3,
                                    HID, b3, out, 0);
}

// round 16
// speedup vs baseline: 1.0856x; 1.0343x over previous
#include <cuda_runtime.h>
#include <cuda_fp16.h>
#include <cstdint>

#define N_NODES 40000
#define N_EDGES 640000
#define IN_DIM  128
#define HID     256

#define SCAN_BLOCKS 40
#define SCAN_CHUNK  1000   // 40 * 1000 = 40000 exactly

// ---------------- device scratch (static, no allocations) ----------------
__device__ int   g_is64;
__device__ int   g_srcs[N_EDGES];
__device__ int   g_dsts[N_EDGES];
__device__ int   g_count[N_NODES];
__device__ int   g_rowstart[N_NODES + 1];
__device__ int   g_cursor[N_NODES];
__device__ int   g_src[N_EDGES];
__device__ int   g_blocksum[SCAN_BLOCKS];

#define WO_L1 0
#define WO_R1 (HID * IN_DIM)
#define WO_L2 (2 * HID * IN_DIM)
#define WO_R2 (2 * HID * IN_DIM + HID * HID)
#define WO_L3 (2 * HID * IN_DIM + 2 * HID * HID)
#define WO_R3 (2 * HID * IN_DIM + 3 * HID * HID)
#define W_TOTAL (2 * HID * IN_DIM + 4 * HID * HID)
#define NX (N_NODES * IN_DIM)
#define NX4 (NX / 4)          // 1,280,000 float4s of x
#define W4  (W_TOTAL / 4)     // 81,920 float4s of weights

__device__ __align__(16) __half g_xh [(size_t)NX];
__device__ __align__(16) __half g_wh [W_TOTAL];
__device__ __align__(16) __half g_agg[(size_t)N_NODES * HID];
__device__ __align__(16) __half g_h  [(size_t)N_NODES * HID];
__device__ __align__(16) __half g_h2 [(size_t)N_NODES * HID];

// ---------------- fused init: zero counts + dtype detect + fp16 convert -----
// Vectorized: float4 in, uint2 (2x half2) out; 4 elements per thread.
__global__ void k_init_convert(const int* __restrict__ ei_w,
                               const float* __restrict__ x,
                               const float* __restrict__ Wl1, const float* __restrict__ Wr1,
                               const float* __restrict__ Wl2, const float* __restrict__ Wr2,
                               const float* __restrict__ Wl3, const float* __restrict__ Wr3) {
    int i = blockIdx.x * blockDim.x + threadIdx.x;
    if (i < N_NODES) g_count[i] = 0;
    if (blockIdx.x == 0) {
        __shared__ int acc;
        if (threadIdx.x == 0) acc = 0;
        __syncthreads();
        int v = 0;
        for (int j = threadIdx.x; j < 2048; j += 256) v |= ei_w[2 * j + 1];
        atomicOr(&acc, v);
        __syncthreads();
        if (threadIdx.x == 0) g_is64 = (acc == 0) ? 1 : 0;
    }
    if (i < NX4) {
        float4 v = ((const float4*)x)[i];
        __half2 a = __floats2half2_rn(v.x, v.y);
        __half2 b = __floats2half2_rn(v.z, v.w);
        ((uint2*)g_xh)[i] = make_uint2(*(uint32_t*)&a, *(uint32_t*)&b);
        return;
    }
    int j = i - NX4;
    if (j >= W4) return;
    int jf = j * 4;           // all WO_* offsets are multiples of 4
    const float* Wsrc; int off;
    if      (jf < WO_R1) { Wsrc = Wl1; off = WO_L1; }
    else if (jf < WO_L2) { Wsrc = Wr1; off = WO_R1; }
    else if (jf < WO_R2) { Wsrc = Wl2; off = WO_L2; }
    else if (jf < WO_L3) { Wsrc = Wr2; off = WO_R2; }
    else if (jf < WO_R3) { Wsrc = Wl3; off = WO_L3; }
    else                 { Wsrc = Wr3; off = WO_R3; }
    float4 v = *(const float4*)&Wsrc[jf - off];
    __half2 a = __floats2half2_rn(v.x, v.y);
    __half2 b = __floats2half2_rn(v.z, v.w);
    ((uint2*)g_wh)[j] = make_uint2(*(uint32_t*)&a, *(uint32_t*)&b);
}

__device__ __forceinline__ int clampN(int v) {
    return v < 0 ? 0 : (v >= N_NODES ? N_NODES - 1 : v);
}

// normalize edge list + histogram dst degrees
__global__ void k_extract_count(const int* __restrict__ ei_w) {
    int e = blockIdx.x * blockDim.x + threadIdx.x;
    if (e >= N_EDGES) return;
    int s, d;
    if (g_is64) {
        const int2* ei64 = (const int2*)ei_w;
        s = ei64[(size_t)e].x;
        d = ei64[(size_t)N_EDGES + e].x;
    } else {
        s = ei_w[e];
        d = ei_w[N_EDGES + e];
    }
    s = clampN(s); d = clampN(d);
    g_srcs[e] = s;
    g_dsts[e] = d;
    atomicAdd(&g_count[d], 1);
}

// ---------------- decoupled scan ----------------
__global__ void k_scan_phase1() {
    __shared__ int sm[1024];
    const int b = blockIdx.x, t = threadIdx.x;
    const int idx = b * SCAN_CHUNK + t;
    int v = (t < SCAN_CHUNK) ? g_count[idx] : 0;
    sm[t] = v;
    __syncthreads();
    for (int off = 1; off < 1024; off <<= 1) {
        int u = (t >= off) ? sm[t - off] : 0;
        __syncthreads();
        sm[t] += u;
        __syncthreads();
    }
    if (t < SCAN_CHUNK) g_rowstart[idx] = sm[t] - v;
    if (t == 1023) g_blocksum[b] = sm[1023];
}

// phase 2+3: cooperative 64-slot scan of the 40 block sums (no serial loop)
__global__ void k_scan_phase23() {
    __shared__ int bs[64];
    const int b = blockIdx.x, t = threadIdx.x;
    if (t < 64) bs[t] = (t < SCAN_BLOCKS) ? g_blocksum[t] : 0;
    __syncthreads();
    #pragma unroll
    for (int off = 1; off < 64; off <<= 1) {
        int u = (t < 64 && t >= off) ? bs[t - off] : 0;
        __syncthreads();
        if (t < 64) bs[t] += u;
        __syncthreads();
    }
    const int off = (b == 0) ? 0 : bs[b - 1];   // exclusive offset for this block
    if (t < SCAN_CHUNK) {
        int idx = b * SCAN_CHUNK + t;
        int rs = g_rowstart[idx] + off;
        g_rowstart[idx] = rs;
        g_cursor[idx]   = rs;
    }
    if (b == 0 && t == 0) g_rowstart[N_NODES] = bs[SCAN_BLOCKS - 1];
}

__global__ void k_fill_src() {
    int e = blockIdx.x * blockDim.x + threadIdx.x;
    if (e < N_EDGES) {
        int pos = atomicAdd(&g_cursor[g_dsts[e]], 1);
        g_src[pos] = g_srcs[e];
    }
}

// ---------------- mean aggregation over in-edges (fp16 in/out, fp32 acc) ----
// 8-edge unroll -> 8 outstanding 16B loads per thread for latency hiding.
template <int D>
__global__ void k_aggregate_h(const __half* __restrict__ x, __half* __restrict__ out) {
    constexpr int TPN = D / 8;        // threads per node, uint4 = 8 halves
    constexpr int NPB = 256 / TPN;
    int node = blockIdx.x * NPB + threadIdx.x / TPN;
    int lane = threadIdx.x % TPN;
    if (node >= N_NODES) return;

    const int beg = g_rowstart[node];
    const int end = g_rowstart[node + 1];
    const uint4* xv = (const uint4*)x;

    float acc[8] = {};
    int j = beg;
    for (; j + 8 <= end; j += 8) {
        uint4 v[8];
        #pragma unroll
        for (int e = 0; e < 8; e++)
            v[e] = xv[(size_t)g_src[j + e] * TPN + lane];
        #pragma unroll
        for (int e = 0; e < 8; e++) {
            #pragma unroll
            for (int q = 0; q < 4; q++) {
                uint32_t w = (&v[e].x)[q];
                float2 f = __half22float2(*(__half2*)&w);
                acc[2 * q + 0] += f.x;
                acc[2 * q + 1] += f.y;
            }
        }
    }
    for (; j + 4 <= end; j += 4) {
        uint4 v[4];
        #pragma unroll
        for (int e = 0; e < 4; e++)
            v[e] = xv[(size_t)g_src[j + e] * TPN + lane];
        #pragma unroll
        for (int e = 0; e < 4; e++) {
            #pragma unroll
            for (int q = 0; q < 4; q++) {
                uint32_t w = (&v[e].x)[q];
                float2 f = __half22float2(*(__half2*)&w);
                acc[2 * q + 0] += f.x;
                acc[2 * q + 1] += f.y;
            }
        }
    }
    for (; j < end; j++) {
        uint4 v = xv[(size_t)g_src[j] * TPN + lane];
        #pragma unroll
        for (int q = 0; q < 4; q++) {
            uint32_t w = (&v.x)[q];
            float2 f = __half22float2(*(__half2*)&w);
            acc[2 * q + 0] += f.x;
            acc[2 * q + 1] += f.y;
        }
    }
    float inv = (end > beg) ? 1.f / (float)(end - beg) : 0.f;
    uint4 r;
    #pragma unroll
    for (int q = 0; q < 4; q++) {
        __half2 hp = __floats2half2_rn(acc[2 * q] * inv, acc[2 * q + 1] * inv);
        (&r.x)[q] = *(uint32_t*)&hp;
    }
    ((uint4*)out)[(size_t)node * TPN + lane] = r;
}

// ---------------- fp16 tensor-core fused dual-source GEMM (proven) ----------
// C[M,256] = A0@W0^T + A1@W1^T + b (optional ReLU); fp32 accumulate.
// BM=BN=128, BK=32 halves; 4-stage cp.async, issue distance 2, one barrier/tile.
__device__ __forceinline__ void mma_f16(float* c,
                                        uint32_t a0, uint32_t a1, uint32_t a2, uint32_t a3,
                                        uint32_t b0, uint32_t b1) {
    asm volatile(
        "mma.sync.aligned.m16n8k16.row.col.f32.f16.f16.f32 "
        "{%0,%1,%2,%3}, {%4,%5,%6,%7}, {%8,%9}, {%0,%1,%2,%3};"
        : "+f"(c[0]), "+f"(c[1]), "+f"(c[2]), "+f"(c[3])
        : "r"(a0), "r"(a1), "r"(a2), "r"(a3), "r"(b0), "r"(b1));
}

#define GLDS  40                       // halves per smem row (80 B)
#define GTILE (128 * GLDS)             // halves per stage buffer (10 KB)
#define GSMEM (8 * GTILE * 2)          // 4 A stages + 4 B stages = 81920 B

__global__ __launch_bounds__(256, 2)
void k_gemm_h(const __half* __restrict__ A0, const __half* __restrict__ W0,
              const __half* __restrict__ A1, const __half* __restrict__ W1,
              int K, const float* __restrict__ bias,
              void* __restrict__ Cout, int relu_half) {
    extern __shared__ __half smh[];    // [As0..As3 | Bs0..Bs3]

    const int t    = threadIdx.x;
    const int warp = t >> 5, lane = t & 31;
    const int g    = lane >> 2, tg = lane & 3;
    const int wm   = warp & 3;                 // M offset 32*wm
    const int wn   = warp >> 2;                // N offset 64*wn
    const int row0 = blockIdx.x * 128;
    const int col0 = blockIdx.y * 128;

    const int lr = t >> 2;                     // 0..63 load row (2 passes)
    const int kq = t & 3;                      // 0..3, 16B (8-half) chunk

    const int tilesPerSrc = K >> 5;
    const int nTiles = 2 * tilesPerSrc;

    float acc[2][8][4] = {};

    auto issue = [&](int tile) {
        const int s = tile & 3;
        const __half* A = (tile < tilesPerSrc) ? A0 : A1;
        const __half* W = (tile < tilesPerSrc) ? W0 : W1;
        const int kt = ((tile < tilesPerSrc) ? tile : tile - tilesPerSrc) << 5;
        #pragma unroll
        for (int p = 0; p < 2; p++) {
            int row = lr + 64 * p;
            uint32_t da = (uint32_t)__cvta_generic_to_shared(
                &smh[s * GTILE + row * GLDS + kq * 8]);
            const __half* ga = &A[(size_t)(row0 + row) * K + kt + kq * 8];
            int sz = (row0 + row < N_NODES) ? 16 : 0;
            asm volatile("cp.async.cg.shared.global [%0], [%1], 16, %2;"
                         :: "r"(da), "l"(ga), "r"(sz));
            uint32_t db = (uint32_t)__cvta_generic_to_shared(
                &smh[4 * GTILE + s * GTILE + row * GLDS + kq * 8]);
            const __half* gw = &W[(size_t)(col0 + row) * K + kt + kq * 8];
            asm volatile("cp.async.cg.shared.global [%0], [%1], 16;"
                         :: "r"(db), "l"(gw));
        }
        asm volatile("cp.async.commit_group;");
    };

    issue(0);
    issue(1);
    for (int tile = 0; tile < nTiles; ++tile) {
        if (tile + 2 < nTiles) {
            issue(tile + 2);
            asm volatile("cp.async.wait_group 2;");
        } else if (tile + 1 < nTiles) {
            asm volatile("cp.async.wait_group 1;");
        } else {
            asm volatile("cp.async.wait_group 0;");
        }
        __syncthreads();                        // single barrier per tile

        const __half* Asb = &smh[(tile & 3) * GTILE];
        const __half* Bsb = &smh[4 * GTILE + (tile & 3) * GTILE];

        #pragma unroll
        for (int kk = 0; kk < 32; kk += 16) {
            uint32_t bf[8][2];
            #pragma unroll
            for (int nt = 0; nt < 8; nt++) {
                int n = wn * 64 + nt * 8 + g;
                bf[nt][0] = *(const uint32_t*)&Bsb[n * GLDS + kk + 2 * tg];
                bf[nt][1] = *(const uint32_t*)&Bsb[n * GLDS + kk + 2 * tg + 8];
            }
            #pragma unroll
            for (int mt = 0; mt < 2; mt++) {
                int r = wm * 32 + mt * 16 + g;
                uint32_t a0 = *(const uint32_t*)&Asb[(r    ) * GLDS + kk + 2 * tg];
                uint32_t a1 = *(const uint32_t*)&Asb[(r + 8) * GLDS + kk + 2 * tg];
                uint32_t a2 = *(const uint32_t*)&Asb[(r    ) * GLDS + kk + 2 * tg + 8];
                uint32_t a3 = *(const uint32_t*)&Asb[(r + 8) * GLDS + kk + 2 * tg + 8];
                #pragma unroll
                for (int nt = 0; nt < 8; nt++)
                    mma_f16(acc[mt][nt], a0, a1, a2, a3, bf[nt][0], bf[nt][1]);
            }
        }
    }

    // epilogue: bias; relu+fp16 store (layers 1-2) or fp32 store (layer 3)
    #pragma unroll
    for (int mt = 0; mt < 2; mt++) {
        int r = row0 + wm * 32 + mt * 16 + g;
        #pragma unroll
        for (int nt = 0; nt < 8; nt++) {
            int col = col0 + wn * 64 + nt * 8 + tg * 2;
            float2 bv = *(const float2*)&bias[col];
            float v0 = acc[mt][nt][0] + bv.x;
            float v1 = acc[mt][nt][1] + bv.y;
            float v2 = acc[mt][nt][2] + bv.x;
            float v3 = acc[mt][nt][3] + bv.y;
            if (relu_half) {
                __half* C = (__half*)Cout;
                __half2 h0 = __floats2half2_rn(fmaxf(v0, 0.f), fmaxf(v1, 0.f));
                __half2 h1 = __floats2half2_rn(fmaxf(v2, 0.f), fmaxf(v3, 0.f));
                if (r < N_NODES)     *(__half2*)&C[(size_t)r * HID + col]       = h0;
                if (r + 8 < N_NODES) *(__half2*)&C[(size_t)(r + 8) * HID + col] = h1;
            } else {
                float* C = (float*)Cout;
                if (r < N_NODES)     *(float2*)&C[(size_t)r * HID + col]       = make_float2(v0, v1);
                if (r + 8 < N_NODES) *(float2*)&C[(size_t)(r + 8) * HID + col] = make_float2(v2, v3);
            }
        }
    }
}

// ---------------- launch ----------------
extern "C" void kernel_launch(void* const* d_in, const int* in_sizes, int n_in,
                              void* d_out, int out_size) {
    const float* x   = (const float*)d_in[0];
    const int*   eiw = (const int*)d_in[1];
    const float* Wl1 = (const float*)d_in[2];
    const float* Wr1 = (const float*)d_in[3];
    const float* b1  = (const float*)d_in[4];
    const float* Wl2 = (const float*)d_in[5];
    const float* Wr2 = (const float*)d_in[6];
    const float* b2  = (const float*)d_in[7];
    const float* Wl3 = (const float*)d_in[8];
    const float* Wr3 = (const float*)d_in[9];
    const float* b3  = (const float*)d_in[10];
    float*       out = (float*)d_out;

    __half *agg, *h, *h2, *xh, *wh;
    cudaGetSymbolAddress((void**)&agg, g_agg);
    cudaGetSymbolAddress((void**)&h,   g_h);
    cudaGetSymbolAddress((void**)&h2,  g_h2);
    cudaGetSymbolAddress((void**)&xh,  g_xh);
    cudaGetSymbolAddress((void**)&wh,  g_wh);

    cudaFuncSetAttribute(k_gemm_h,
                         cudaFuncAttributeMaxDynamicSharedMemorySize, GSMEM);

    // fused init (zero counts + detect + vectorized fp16 convert), then CSR
    k_init_convert<<<(NX4 + W4 + 255) / 256, 256>>>(eiw, x, Wl1, Wr1,
                                                    Wl2, Wr2, Wl3, Wr3);
    k_extract_count<<<(N_EDGES + 255) / 256, 256>>>(eiw);
    k_scan_phase1<<<SCAN_BLOCKS, 1024>>>();
    k_scan_phase23<<<SCAN_BLOCKS, 1024>>>();
    k_fill_src<<<(N_EDGES + 255) / 256, 256>>>();

    dim3 ggrid((N_NODES + 127) / 128, HID / 128);   // 313 x 2

    // Layer 1: 128 -> 256, relu, fp16 out
    k_aggregate_h<IN_DIM><<<(N_NODES + 15) / 16, 256>>>(xh, agg);
    k_gemm_h<<<ggrid, 256, GSMEM>>>(agg, wh + WO_L1, xh, wh + WO_R1,
                                    IN_DIM, b1, h, 1);

    // Layer 2: 256 -> 256, relu, fp16 out
    k_aggregate_h<HID><<<(N_NODES + 7) / 8, 256>>>(h, agg);
    k_gemm_h<<<ggrid, 256, GSMEM>>>(agg, wh + WO_L2, h, wh + WO_R2,
                                    HID, b2, h2, 1);

    // Layer 3: 256 -> 256, fp32 out to d_out
    k_aggregate_h<HID><<<(N_NODES + 7) / 8, 256>>>(h2, agg);
    k_gemm_h<<<ggrid, 256, GSMEM>>>(agg, wh + WO_L3, h2, wh + WO_R3,
                                    HID, b3, out, 0);
}